// round 11
// baseline (speedup 1.0000x reference)
#include <cuda_runtime.h>
#include <cstdint>

#define BB 64
#define HH 1024
#define WW 1024
#define NN 256
#define MAX_ITERS 20
#define W9 (1.0f/9.0f)

// scratch
__device__ int2 g_end[BB * NN];      // end coords after gravity (x,y)
__device__ int  g_meta[BB * NN];     // winner | leader<<8 | has<<16

// ---------------------------------------------------------------------------
// Kernel 1: gravity_move, TWO points per warp (ILP over the dependent chain),
// 2 warps/block. Interior fast path: 27 aligned LDG.128 per tile, double-
// buffered SMEM, one syncwarp per iteration covering both points' loads.
// ---------------------------------------------------------------------------
__global__ void __launch_bounds__(64) gravity_kernel(
    const float* __restrict__ depth, const int* __restrict__ points)
{
    const int w     = threadIdx.x >> 5;
    const int lane  = threadIdx.x & 31;
    const int pbase = blockIdx.x * 4 + w * 2;     // grid = B*N/4; pts pbase, pbase+1
    const int b     = pbase >> 8;                 // both points in same batch
    const float* dep = depth + (size_t)b * HH * WW;

    int2 p0 = *(const int2*)(points + pbase * 2);
    int2 p1 = *(const int2*)(points + pbase * 2 + 2);
    int px0 = p0.x, py0 = p0.y;
    int px1 = p1.x, py1 = p1.y;

    __shared__ __align__(16) float tile[2][2][2][128];  // [warp][pt][buf][9x12]
    float* T0base = &tile[w][0][0][0];
    float* T1base = &tile[w][1][0][0];

    // ---- loop-invariant per-lane constants (shared by both points) ----
    const int vr  = lane / 3, vseg = lane - vr * 3;
    const int vgo = vr * WW + vseg * 4;
    const int vso = vr * 12 + vseg * 4;
    const bool vld = (lane < 27);

    const int r0 = lane / 9,        c0 = lane - r0 * 9;
    const int e1 = lane + 32;
    const int r1 = e1 / 9,          c1 = e1 - r1 * 9;
    const int e2 = lane + 64;
    const int r2 = e2 / 9,          c2 = e2 - r2 * 9;
    const bool l3 = (lane < 17);

    const int cA  = lane;
    const int rA  = cA / 7;
    const int dyA = rA - 3,  dxA = cA - rA * 7 - 3;
    const int cB  = lane + 32;
    const int rB  = cB / 7;
    const int dyB = rB - 3,  dxB = cB - rB * 7 - 3;
    const bool hasB = (cB < 49);
    const int sAo = (dyA + 3) * 12 + (dxA + 3);
    const int sBo = (dyB + 3) * 12 + (dxB + 3);

    // load one 9x9 window (interior: 27x LDG.128 into 9x12; border: guarded)
    auto load_tile = [&](float* T, int px, int py, bool interior) -> int {
        const int by = py - 4, bx = px - 4;
        if (interior) {
            const int bx4 = bx & ~3;
            if (vld) {
                float4 v = __ldg((const float4*)(dep + by * WW + bx4 + vgo));
                *(float4*)(T + vso) = v;
            }
            return bx - bx4;
        } else {
            {
                int gy = by + r0, gx = bx + c0;
                T[r0 * 12 + c0] = (gy >= 0 && gy < HH && gx >= 0 && gx < WW)
                                      ? __ldg(dep + gy * WW + gx) : 0.0f;
            }
            {
                int gy = by + r1, gx = bx + c1;
                T[r1 * 12 + c1] = (gy >= 0 && gy < HH && gx >= 0 && gx < WW)
                                      ? __ldg(dep + gy * WW + gx) : 0.0f;
            }
            if (l3) {
                int gy = by + r2, gx = bx + c2;
                T[r2 * 12 + c2] = (gy >= 0 && gy < HH && gx >= 0 && gx < WW)
                                      ? __ldg(dep + gy * WW + gx) : 0.0f;
            }
            return 0;
        }
    };

    // one hill-climb step; updates px,py; returns moved
    auto step = [&](const float* T, int& px, int& py, bool interior, int sh) -> bool {
        unsigned uA, uB = 0u;
        if (interior) {
            const float* p = T + sAo + sh;
            float a = 0.0f;
            #pragma unroll
            for (int i2 = 0; i2 < 3; ++i2)
                #pragma unroll
                for (int j2 = 0; j2 < 3; ++j2)
                    a = fmaf(p[i2 * 12 + j2], W9, a);
            unsigned ua = __float_as_uint(a);
            uA = ((int)ua >= 0) ? (ua | 0x80000000u) : ~ua;

            if (hasB) {
                const float* q = T + sBo + sh;
                float b2 = 0.0f;
                #pragma unroll
                for (int i2 = 0; i2 < 3; ++i2)
                    #pragma unroll
                    for (int j2 = 0; j2 < 3; ++j2)
                        b2 = fmaf(q[i2 * 12 + j2], W9, b2);
                unsigned ub = __float_as_uint(b2);
                uB = ((int)ub >= 0) ? (ub | 0x80000000u) : ~ub;
            }
        } else {
            const int by = py - 4, bx = px - 4;
            {
                int yc = min(max(py + dyA, 0), HH - 1);
                int xc = min(max(px + dxA, 0), WW - 1);
                const float* p = T + (yc - by - 1) * 12 + (xc - bx - 1);
                float a = 0.0f;
                #pragma unroll
                for (int i2 = 0; i2 < 3; ++i2)
                    #pragma unroll
                    for (int j2 = 0; j2 < 3; ++j2)
                        a = fmaf(p[i2 * 12 + j2], W9, a);
                unsigned ua = __float_as_uint(a);
                uA = ((int)ua >= 0) ? (ua | 0x80000000u) : ~ua;
            }
            if (hasB) {
                int yc = min(max(py + dyB, 0), HH - 1);
                int xc = min(max(px + dxB, 0), WW - 1);
                const float* q = T + (yc - by - 1) * 12 + (xc - bx - 1);
                float b2 = 0.0f;
                #pragma unroll
                for (int i2 = 0; i2 < 3; ++i2)
                    #pragma unroll
                    for (int j2 = 0; j2 < 3; ++j2)
                        b2 = fmaf(q[i2 * 12 + j2], W9, b2);
                unsigned ub = __float_as_uint(b2);
                uB = ((int)ub >= 0) ? (ub | 0x80000000u) : ~ub;
            }
        }

        // warp argmax, exact first-index tie-break
        unsigned wmax = __reduce_max_sync(0xffffffffu, max(uA, uB));
        unsigned balA = __ballot_sync(0xffffffffu, uA == wmax);
        unsigned balB = __ballot_sync(0xffffffffu, uB == wmax);
        int besti = balA ? (__ffs(balA) - 1) : (__ffs(balB) + 31);

        int rr = besti / 7;
        int ny = min(max(py + rr - 3, 0), HH - 1);
        int nx = min(max(px + besti - rr * 7 - 3, 0), WW - 1);
        bool moved = (nx != px) | (ny != py);
        px = nx; py = ny;
        return moved;
    };

    bool act0 = true, act1 = true;
    int it0 = 0, it1 = 0;

    while (act0 | act1) {                          // warp-uniform flags
        bool int0 = false, int1 = false;
        int  sh0 = 0, sh1 = 0;
        float *T0 = T0base + ((it0 & 1) << 7);
        float *T1 = T1base + ((it1 & 1) << 7);

        if (act0) {
            int0 = (px0 >= 4) & (px0 <= WW - 8) & (py0 >= 4) & (py0 <= HH - 5);
            sh0  = load_tile(T0, px0, py0, int0);
        }
        if (act1) {
            int1 = (px1 >= 4) & (px1 <= WW - 8) & (py1 >= 4) & (py1 <= HH - 5);
            sh1  = load_tile(T1, px1, py1, int1);
        }
        __syncwarp();

        if (act0) {
            bool moved = step(T0, px0, py0, int0, sh0);
            ++it0;
            act0 = moved & (it0 < MAX_ITERS);
        }
        if (act1) {
            bool moved = step(T1, px1, py1, int1, sh1);
            ++it1;
            act1 = moved & (it1 < MAX_ITERS);
        }
    }

    if (lane == 0) {
        g_end[pbase]     = make_int2(px0, py0);
        g_end[pbase + 1] = make_int2(px1, py1);
    }
}

// ---------------------------------------------------------------------------
// Kernel 2: pairwise overlap stats, one WARP per point (lane covers 8 j's),
// 32 blocks per batch. Packed-key REDUX reductions, exact tie-breaks.
// ---------------------------------------------------------------------------
__global__ void __launch_bounds__(256) pairwise_kernel(
    const int* __restrict__ points)
{
    const int w    = threadIdx.x >> 5;
    const int lane = threadIdx.x & 31;
    const int blkInBatch = blockIdx.x & 31;       // 32 blocks per batch
    const int b    = blockIdx.x >> 5;
    const int base = b * NN;

    __shared__ int ex[NN], ey[NN], sx[NN], sy[NN];
    const int t = threadIdx.x;
    {
        int2 e = g_end[base + t];
        ex[t] = e.x;  ey[t] = e.y;
        int2 s = *(const int2*)(points + (base + t) * 2);
        sx[t] = s.x;  sy[t] = s.y;
    }
    __syncthreads();

    const int i   = blkInBatch * 8 + w;
    const int exi = ex[i], eyi = ey[i];

    int cnt = 0;
    unsigned minlead = 255u;
    unsigned key = 0xffffffffu;                    // (sd<<8)|j, sd < 2^21

    #pragma unroll
    for (int m = 0; m < 8; ++m) {
        int j   = lane + 32 * m;
        int ddx = exi - ex[j], ddy = eyi - ey[j];
        int de  = ddx * ddx + ddy * ddy;
        if (de < 4) {                              // dist < 2.0 <=> sq < 4
            cnt++;
            minlead = min(minlead, (unsigned)j);   // argmax(ov) = first True
            int sdx = sx[j] - exi, sdy = sy[j] - eyi;
            unsigned sd = (unsigned)(sdx * sdx + sdy * sdy);
            key = min(key, (sd << 8) | (unsigned)j);
        }
    }
    cnt     = __reduce_add_sync(0xffffffffu, cnt);
    minlead = __reduce_min_sync(0xffffffffu, minlead);
    key     = __reduce_min_sync(0xffffffffu, key);

    if (lane == 0)
        g_meta[base + i] = (int)(key & 255u) | ((int)minlead << 8) | ((cnt > 1) << 16);
}

// ---------------------------------------------------------------------------
// Kernel 3: finalize coordinates + peak (exact row-major 3x3 fma chain).
// ---------------------------------------------------------------------------
__global__ void __launch_bounds__(128) finalize_kernel(
    const float* __restrict__ depth, const int* __restrict__ points,
    float* __restrict__ out)
{
    const int gid  = blockIdx.x * 128 + threadIdx.x;   // 0..16383
    const int b    = gid >> 8;
    const int base = b * NN;
    const int i    = gid & 255;

    const int meta   = g_meta[gid];
    const int leader = (meta >> 8) & 0xff;
    const bool has   = (meta >> 16) & 1;
    const int wol    = g_meta[base + leader] & 0xff;   // winner[leader]

    int fx, fy;
    if (has) {
        if (i == wol) {
            int2 e = g_end[base + leader];
            fx = e.x; fy = e.y;
        } else {
            int2 s = *(const int2*)(points + gid * 2);
            fx = s.x; fy = s.y;
        }
    } else {
        int2 e = g_end[gid];
        fx = e.x; fy = e.y;
    }

    const float* dep = depth + (size_t)b * HH * WW;
    float acc = 0.0f;
    #pragma unroll
    for (int u = -1; u <= 1; ++u)
        #pragma unroll
        for (int v = -1; v <= 1; ++v) {
            int gy = fy + u, gx = fx + v;
            float val = (gy >= 0 && gy < HH && gx >= 0 && gx < WW)
                            ? __ldg(dep + gy * WW + gx) : 0.0f;
            acc = fmaf(val, W9, acc);
        }

    out[gid * 2 + 0] = (float)fx;
    out[gid * 2 + 1] = (float)fy;
    out[BB * NN * 2 + gid] = acc;
}

// ---------------------------------------------------------------------------
extern "C" void kernel_launch(void* const* d_in, const int* in_sizes, int n_in,
                              void* d_out, int out_size)
{
    const float* depth  = (const float*)d_in[0];   // (64,1,1024,1024) f32
    const int*   points = (const int*)d_in[1];     // (64,256,2) i32
    float* out = (float*)d_out;                    // end (B,N,2) ++ peak (B,N)

    gravity_kernel <<<(BB * NN) / 4, 64>>>(depth, points);
    pairwise_kernel<<<BB * 32,       256>>>(points);
    finalize_kernel<<<(BB * NN) / 128, 128>>>(depth, points, out);
}

// round 12
// speedup vs baseline: 1.0617x; 1.0617x over previous
#include <cuda_runtime.h>
#include <cstdint>

#define BB 64
#define HH 1024
#define WW 1024
#define NN 256
#define MAX_ITERS 20
#define W9 (1.0f/9.0f)

// scratch
__device__ int2 g_end[BB * NN];      // end coords after gravity (x,y)
__device__ int  g_meta[BB * NN];     // winner | leader<<8 | has<<16

// ---------------------------------------------------------------------------
// Kernel 1: gravity_move, one warp per point, 2 warps/block.
// Interior fast path: one round of 27 aligned LDG.128 loads the 9x12 window.
// Double-buffered SMEM tile -> single syncwarp per iteration.
// (byte-identical to the round-10 best)
// ---------------------------------------------------------------------------
__global__ void __launch_bounds__(64) gravity_kernel(
    const float* __restrict__ depth, const int* __restrict__ points)
{
    const int w    = threadIdx.x >> 5;
    const int lane = threadIdx.x & 31;
    const int pidx = blockIdx.x * 2 + w;          // grid = B*N/2
    const int b    = pidx >> 8;                   // N = 256
    const float* dep = depth + (size_t)b * HH * WW;

    int2 pt = *(const int2*)(points + pidx * 2);
    int px = pt.x, py = pt.y;

    __shared__ __align__(16) float tile[2][2][128];   // [warp][buf][9x12 pitch]
    float* Tbase = &tile[w][0][0];

    // ---- loop-invariant per-lane constants ----
    const int vr  = lane / 3, vseg = lane - vr * 3;
    const int vgo = vr * WW + vseg * 4;           // global offset from (by,bx4)
    const int vso = vr * 12 + vseg * 4;           // smem offset
    const bool vld = (lane < 27);

    const int r0 = lane / 9,        c0 = lane - r0 * 9;
    const int e1 = lane + 32;
    const int r1 = e1 / 9,          c1 = e1 - r1 * 9;
    const int e2 = lane + 64;
    const int r2 = e2 / 9,          c2 = e2 - r2 * 9;
    const bool l3 = (lane < 17);

    const int cA  = lane;
    const int rA  = cA / 7;
    const int dyA = rA - 3,  dxA = cA - rA * 7 - 3;
    const int cB  = lane + 32;
    const int rB  = cB / 7;
    const int dyB = rB - 3,  dxB = cB - rB * 7 - 3;
    const bool hasB = (cB < 49);
    const int sAo = (dyA + 3) * 12 + (dxA + 3);   // top-left of 3x3, pitch 12
    const int sBo = (dyB + 3) * 12 + (dxB + 3);

    for (int it = 0; it < MAX_ITERS; ++it) {
        float* T = Tbase + ((it & 1) << 7);       // alternate 128-float buffers
        const int by = py - 4, bx = px - 4;
        const bool interior = (px >= 4) & (px <= WW - 8) &
                              (py >= 4) & (py <= HH - 5);   // warp-uniform
        int sh = 0;

        if (interior) {
            const int bx4 = bx & ~3;
            sh = bx - bx4;
            if (vld) {
                float4 v = __ldg((const float4*)(dep + by * WW + bx4 + vgo));
                *(float4*)(T + vso) = v;
            }
        } else {
            {
                int gy = by + r0, gx = bx + c0;
                T[r0 * 12 + c0] = (gy >= 0 && gy < HH && gx >= 0 && gx < WW)
                                      ? __ldg(dep + gy * WW + gx) : 0.0f;
            }
            {
                int gy = by + r1, gx = bx + c1;
                T[r1 * 12 + c1] = (gy >= 0 && gy < HH && gx >= 0 && gx < WW)
                                      ? __ldg(dep + gy * WW + gx) : 0.0f;
            }
            if (l3) {
                int gy = by + r2, gx = bx + c2;
                T[r2 * 12 + c2] = (gy >= 0 && gy < HH && gx >= 0 && gx < WW)
                                      ? __ldg(dep + gy * WW + gx) : 0.0f;
            }
        }
        __syncwarp();                              // store -> load ordering

        unsigned uA, uB = 0u;
        if (interior) {
            const float* p = T + sAo + sh;
            float a = 0.0f;
            #pragma unroll
            for (int i2 = 0; i2 < 3; ++i2)
                #pragma unroll
                for (int j2 = 0; j2 < 3; ++j2)
                    a = fmaf(p[i2 * 12 + j2], W9, a);
            unsigned ua = __float_as_uint(a);
            uA = ((int)ua >= 0) ? (ua | 0x80000000u) : ~ua;

            if (hasB) {
                const float* q = T + sBo + sh;
                float b2 = 0.0f;
                #pragma unroll
                for (int i2 = 0; i2 < 3; ++i2)
                    #pragma unroll
                    for (int j2 = 0; j2 < 3; ++j2)
                        b2 = fmaf(q[i2 * 12 + j2], W9, b2);
                unsigned ub = __float_as_uint(b2);
                uB = ((int)ub >= 0) ? (ub | 0x80000000u) : ~ub;
            }
        } else {
            {
                int yc = min(max(py + dyA, 0), HH - 1);
                int xc = min(max(px + dxA, 0), WW - 1);
                const float* p = T + (yc - by - 1) * 12 + (xc - bx - 1);
                float a = 0.0f;
                #pragma unroll
                for (int i2 = 0; i2 < 3; ++i2)
                    #pragma unroll
                    for (int j2 = 0; j2 < 3; ++j2)
                        a = fmaf(p[i2 * 12 + j2], W9, a);
                unsigned ua = __float_as_uint(a);
                uA = ((int)ua >= 0) ? (ua | 0x80000000u) : ~ua;
            }
            if (hasB) {
                int yc = min(max(py + dyB, 0), HH - 1);
                int xc = min(max(px + dxB, 0), WW - 1);
                const float* q = T + (yc - by - 1) * 12 + (xc - bx - 1);
                float b2 = 0.0f;
                #pragma unroll
                for (int i2 = 0; i2 < 3; ++i2)
                    #pragma unroll
                    for (int j2 = 0; j2 < 3; ++j2)
                        b2 = fmaf(q[i2 * 12 + j2], W9, b2);
                unsigned ub = __float_as_uint(b2);
                uB = ((int)ub >= 0) ? (ub | 0x80000000u) : ~ub;
            }
        }

        // warp argmax, exact first-index tie-break:
        unsigned wmax = __reduce_max_sync(0xffffffffu, max(uA, uB));
        unsigned balA = __ballot_sync(0xffffffffu, uA == wmax);
        unsigned balB = __ballot_sync(0xffffffffu, uB == wmax);
        int besti = balA ? (__ffs(balA) - 1) : (__ffs(balB) + 31);

        int rr = besti / 7;
        int ny = min(max(py + rr - 3, 0), HH - 1);
        int nx = min(max(px + besti - rr * 7 - 3, 0), WW - 1);
        bool moved = (nx != px) | (ny != py);
        px = nx; py = ny;
        if (!moved) break;                        // fixed point stays fixed
    }

    if (lane == 0) g_end[pidx] = make_int2(px, py);
}

// ---------------------------------------------------------------------------
// Kernel 2: pairwise overlap stats. 8 blocks per batch; each block stages the
// batch once and its 8 warps each handle 4 points (32 points per block).
// Packed-key REDUX reductions, exact tie-breaks.
// ---------------------------------------------------------------------------
__global__ void __launch_bounds__(256) pairwise_kernel(
    const int* __restrict__ points)
{
    const int w    = threadIdx.x >> 5;
    const int lane = threadIdx.x & 31;
    const int blkInBatch = blockIdx.x & 7;        // 8 blocks per batch
    const int b    = blockIdx.x >> 3;
    const int base = b * NN;

    __shared__ int ex[NN], ey[NN], sx[NN], sy[NN];
    const int t = threadIdx.x;
    {
        int2 e = g_end[base + t];
        ex[t] = e.x;  ey[t] = e.y;
        int2 s = *(const int2*)(points + (base + t) * 2);
        sx[t] = s.x;  sy[t] = s.y;
    }
    __syncthreads();

    #pragma unroll
    for (int k = 0; k < 4; ++k) {
        const int i   = blkInBatch * 32 + w * 4 + k;
        const int exi = ex[i], eyi = ey[i];

        int cnt = 0;
        unsigned minlead = 255u;
        unsigned key = 0xffffffffu;                // (sd<<8)|j, sd < 2^21

        #pragma unroll
        for (int m = 0; m < 8; ++m) {
            int j   = lane + 32 * m;
            int ddx = exi - ex[j], ddy = eyi - ey[j];
            int de  = ddx * ddx + ddy * ddy;
            if (de < 4) {                          // dist < 2.0 <=> sq < 4
                cnt++;
                minlead = min(minlead, (unsigned)j);   // argmax(ov) = first True
                int sdx = sx[j] - exi, sdy = sy[j] - eyi;
                unsigned sd = (unsigned)(sdx * sdx + sdy * sdy);
                key = min(key, (sd << 8) | (unsigned)j);
            }
        }
        cnt     = __reduce_add_sync(0xffffffffu, cnt);
        minlead = __reduce_min_sync(0xffffffffu, minlead);
        key     = __reduce_min_sync(0xffffffffu, key);

        if (lane == 0)
            g_meta[base + i] = (int)(key & 255u) | ((int)minlead << 8) | ((cnt > 1) << 16);
    }
}

// ---------------------------------------------------------------------------
// Kernel 3: finalize coordinates + peak (exact row-major 3x3 fma chain).
// (byte-identical to the round-10 best)
// ---------------------------------------------------------------------------
__global__ void __launch_bounds__(128) finalize_kernel(
    const float* __restrict__ depth, const int* __restrict__ points,
    float* __restrict__ out)
{
    const int gid  = blockIdx.x * 128 + threadIdx.x;   // 0..16383
    const int b    = gid >> 8;
    const int base = b * NN;
    const int i    = gid & 255;

    const int meta   = g_meta[gid];
    const int leader = (meta >> 8) & 0xff;
    const bool has   = (meta >> 16) & 1;
    const int wol    = g_meta[base + leader] & 0xff;   // winner[leader]

    int fx, fy;
    if (has) {
        if (i == wol) {
            int2 e = g_end[base + leader];
            fx = e.x; fy = e.y;
        } else {
            int2 s = *(const int2*)(points + gid * 2);
            fx = s.x; fy = s.y;
        }
    } else {
        int2 e = g_end[gid];
        fx = e.x; fy = e.y;
    }

    const float* dep = depth + (size_t)b * HH * WW;
    float acc = 0.0f;
    #pragma unroll
    for (int u = -1; u <= 1; ++u)
        #pragma unroll
        for (int v = -1; v <= 1; ++v) {
            int gy = fy + u, gx = fx + v;
            float val = (gy >= 0 && gy < HH && gx >= 0 && gx < WW)
                            ? __ldg(dep + gy * WW + gx) : 0.0f;
            acc = fmaf(val, W9, acc);
        }

    out[gid * 2 + 0] = (float)fx;
    out[gid * 2 + 1] = (float)fy;
    out[BB * NN * 2 + gid] = acc;
}

// ---------------------------------------------------------------------------
extern "C" void kernel_launch(void* const* d_in, const int* in_sizes, int n_in,
                              void* d_out, int out_size)
{
    const float* depth  = (const float*)d_in[0];   // (64,1,1024,1024) f32
    const int*   points = (const int*)d_in[1];     // (64,256,2) i32
    float* out = (float*)d_out;                    // end (B,N,2) ++ peak (B,N)

    gravity_kernel <<<(BB * NN) / 2, 64>>>(depth, points);
    pairwise_kernel<<<BB * 8,        256>>>(points);
    finalize_kernel<<<(BB * NN) / 128, 128>>>(depth, points, out);
}

// round 13
// speedup vs baseline: 1.0947x; 1.0311x over previous
#include <cuda_runtime.h>
#include <cstdint>

#define BB 64
#define HH 1024
#define WW 1024
#define NN 256
#define MAX_ITERS 20
#define W9 (1.0f/9.0f)
#define P15 20               // tile pitch (15-wide rows + slack)

// scratch
__device__ int2 g_end[BB * NN];      // end coords after gravity (x,y)
__device__ int  g_meta[BB * NN];     // winner | leader<<8 | has<<16

// ---------------------------------------------------------------------------
// Kernel 1: gravity_move, one warp per point, 2 warps/block.
// Interior fast path: 15x15 raw tile via 75 aligned LDG.128 -> TWO argmax
// iterations per global round trip (2nd runs purely from SMEM).
// ---------------------------------------------------------------------------
__global__ void __launch_bounds__(64) gravity_kernel(
    const float* __restrict__ depth, const int* __restrict__ points)
{
    const int w    = threadIdx.x >> 5;
    const int lane = threadIdx.x & 31;
    const int pidx = blockIdx.x * 2 + w;          // grid = B*N/2
    const int b    = pidx >> 8;                   // N = 256
    const float* dep = depth + (size_t)b * HH * WW;

    int2 pt = *(const int2*)(points + pidx * 2);
    int px = pt.x, py = pt.y;

    __shared__ __align__(16) float tile[2][2][15 * P15 + 4];  // [warp][buf][]
    float* Tb0 = &tile[w][0][0];
    float* Tb1 = &tile[w][1][0];

    // ---- loop-invariant per-lane constants ----
    // 15x15 vector-load slots: e = lane+32k (k=0..2), e<75: row e/5, seg e%5
    const int v0r = lane / 5,        v0s = lane - v0r * 5;
    const int ev1 = lane + 32;
    const int v1r = ev1 / 5,         v1s = ev1 - v1r * 5;
    const int ev2 = lane + 64;
    const int v2r = ev2 / 5,         v2s = ev2 - v2r * 5;
    const bool vl2 = (ev2 < 75);                  // lane < 11
    const int vg0 = v0r * WW + v0s * 4,  vs0 = v0r * P15 + v0s * 4;
    const int vg1 = v1r * WW + v1s * 4,  vs1 = v1r * P15 + v1s * 4;
    const int vg2 = v2r * WW + v2s * 4,  vs2 = v2r * P15 + v2s * 4;

    // scalar border-load slots (elements lane, lane+32, lane+64 of 9x9)
    const int r0 = lane / 9,        c0 = lane - r0 * 9;
    const int e1 = lane + 32;
    const int r1 = e1 / 9,          c1 = e1 - r1 * 9;
    const int e2 = lane + 64;
    const int r2 = e2 / 9,          c2 = e2 - r2 * 9;
    const bool l3 = (lane < 17);

    // candidate cells: lane and lane+32 (cells 0..48)
    const int cA  = lane;
    const int rA  = cA / 7;
    const int dyA = rA - 3,  dxA = cA - rA * 7 - 3;
    const int cB  = lane + 32;
    const int rB  = cB / 7;
    const int dyB = rB - 3,  dxB = cB - rB * 7 - 3;
    const bool hasB = (cB < 49);
    // interior-15: 3x3 top-left relative to tile origin, center at (7, 7+sh)
    const int sA15 = (dyA + 6) * P15 + (dxA + 6);
    const int sB15 = (dyB + 6) * P15 + (dxB + 6);
    // border (9x9 at pitch P15): top-left relative to (by,bx), center (4,4)
    const int sA9  = (dyA + 3) * P15 + (dxA + 3);
    const int sB9  = (dyB + 3) * P15 + (dxB + 3);

    // unclipped candidate eval + warp argmax (exact first-index tie-break)
    auto evalAB = [&](const float* T, int off) -> int {
        unsigned uA, uB = 0u;
        {
            const float* p = T + sA15 + off;
            float a = 0.0f;
            #pragma unroll
            for (int i2 = 0; i2 < 3; ++i2)
                #pragma unroll
                for (int j2 = 0; j2 < 3; ++j2)
                    a = fmaf(p[i2 * P15 + j2], W9, a);
            unsigned ua = __float_as_uint(a);
            uA = ((int)ua >= 0) ? (ua | 0x80000000u) : ~ua;
        }
        if (hasB) {
            const float* q = T + sB15 + off;
            float b2 = 0.0f;
            #pragma unroll
            for (int i2 = 0; i2 < 3; ++i2)
                #pragma unroll
                for (int j2 = 0; j2 < 3; ++j2)
                    b2 = fmaf(q[i2 * P15 + j2], W9, b2);
            unsigned ub = __float_as_uint(b2);
            uB = ((int)ub >= 0) ? (ub | 0x80000000u) : ~ub;
        }
        unsigned wmax = __reduce_max_sync(0xffffffffu, max(uA, uB));
        unsigned balA = __ballot_sync(0xffffffffu, uA == wmax);
        unsigned balB = __ballot_sync(0xffffffffu, uB == wmax);
        return balA ? (__ffs(balA) - 1) : (__ffs(balB) + 31);
    };

    int it = 0, trip = 0;
    bool done = false;

    while (!done) {
        float* T = (trip & 1) ? Tb1 : Tb0;
        ++trip;
        // interior-15: both steps' windows in-image, clips no-ops,
        // aligned cols bx4..bx4+19 in-row
        const bool int15 = (px >= 7) & (px <= WW - 13) &
                           (py >= 7) & (py <= HH - 8);     // warp-uniform

        if (int15) {
            const int by = py - 7, bx = px - 7;
            const int bx4 = bx & ~3;
            const int sh = bx - bx4;
            const float* base = dep + by * WW + bx4;
            {
                float4 v = __ldg((const float4*)(base + vg0));
                *(float4*)(T + vs0) = v;
            }
            {
                float4 v = __ldg((const float4*)(base + vg1));
                *(float4*)(T + vs1) = v;
            }
            if (vl2) {
                float4 v = __ldg((const float4*)(base + vg2));
                *(float4*)(T + vs2) = v;
            }
            __syncwarp();

            // ---- step 1 ----
            int besti = evalAB(T, sh);
            int rr  = besti / 7;
            int mdy = rr - 3, mdx = besti - rr * 7 - 3;
            px += mdx; py += mdy; ++it;
            if (besti == 24 || it >= MAX_ITERS) { done = true; continue; }

            // ---- step 2 (same tile, shifted center) ----
            int besti2 = evalAB(T, sh + mdy * P15 + mdx);
            int rr2  = besti2 / 7;
            int m2y = rr2 - 3, m2x = besti2 - rr2 * 7 - 3;
            px += m2x; py += m2y; ++it;
            if (besti2 == 24 || it >= MAX_ITERS) { done = true; }
        } else {
            // ---- border: guarded 9x9 load (pitch P15), clipped candidates ----
            const int by = py - 4, bx = px - 4;
            {
                int gy = by + r0, gx = bx + c0;
                T[r0 * P15 + c0] = (gy >= 0 && gy < HH && gx >= 0 && gx < WW)
                                       ? __ldg(dep + gy * WW + gx) : 0.0f;
            }
            {
                int gy = by + r1, gx = bx + c1;
                T[r1 * P15 + c1] = (gy >= 0 && gy < HH && gx >= 0 && gx < WW)
                                       ? __ldg(dep + gy * WW + gx) : 0.0f;
            }
            if (l3) {
                int gy = by + r2, gx = bx + c2;
                T[r2 * P15 + c2] = (gy >= 0 && gy < HH && gx >= 0 && gx < WW)
                                       ? __ldg(dep + gy * WW + gx) : 0.0f;
            }
            __syncwarp();

            unsigned uA, uB = 0u;
            {
                int yc = min(max(py + dyA, 0), HH - 1);
                int xc = min(max(px + dxA, 0), WW - 1);
                const float* p = T + (yc - by - 1) * P15 + (xc - bx - 1);
                float a = 0.0f;
                #pragma unroll
                for (int i2 = 0; i2 < 3; ++i2)
                    #pragma unroll
                    for (int j2 = 0; j2 < 3; ++j2)
                        a = fmaf(p[i2 * P15 + j2], W9, a);
                unsigned ua = __float_as_uint(a);
                uA = ((int)ua >= 0) ? (ua | 0x80000000u) : ~ua;
            }
            if (hasB) {
                int yc = min(max(py + dyB, 0), HH - 1);
                int xc = min(max(px + dxB, 0), WW - 1);
                const float* q = T + (yc - by - 1) * P15 + (xc - bx - 1);
                float b2 = 0.0f;
                #pragma unroll
                for (int i2 = 0; i2 < 3; ++i2)
                    #pragma unroll
                    for (int j2 = 0; j2 < 3; ++j2)
                        b2 = fmaf(q[i2 * P15 + j2], W9, b2);
                unsigned ub = __float_as_uint(b2);
                uB = ((int)ub >= 0) ? (ub | 0x80000000u) : ~ub;
            }

            unsigned wmax = __reduce_max_sync(0xffffffffu, max(uA, uB));
            unsigned balA = __ballot_sync(0xffffffffu, uA == wmax);
            unsigned balB = __ballot_sync(0xffffffffu, uB == wmax);
            int besti = balA ? (__ffs(balA) - 1) : (__ffs(balB) + 31);

            int rr = besti / 7;
            int ny = min(max(py + rr - 3, 0), HH - 1);
            int nx = min(max(px + besti - rr * 7 - 3, 0), WW - 1);
            bool moved = (nx != px) | (ny != py);
            px = nx; py = ny; ++it;
            if (!moved || it >= MAX_ITERS) done = true;
        }
    }

    if (lane == 0) g_end[pidx] = make_int2(px, py);
}

// ---------------------------------------------------------------------------
// Kernel 2: pairwise overlap stats. 8 blocks per batch; 8 warps x 4 points.
// Packed-key REDUX reductions, exact tie-breaks.
// ---------------------------------------------------------------------------
__global__ void __launch_bounds__(256) pairwise_kernel(
    const int* __restrict__ points)
{
    const int w    = threadIdx.x >> 5;
    const int lane = threadIdx.x & 31;
    const int blkInBatch = blockIdx.x & 7;        // 8 blocks per batch
    const int b    = blockIdx.x >> 3;
    const int base = b * NN;

    __shared__ int ex[NN], ey[NN], sx[NN], sy[NN];
    const int t = threadIdx.x;
    {
        int2 e = g_end[base + t];
        ex[t] = e.x;  ey[t] = e.y;
        int2 s = *(const int2*)(points + (base + t) * 2);
        sx[t] = s.x;  sy[t] = s.y;
    }
    __syncthreads();

    #pragma unroll
    for (int k = 0; k < 4; ++k) {
        const int i   = blkInBatch * 32 + w * 4 + k;
        const int exi = ex[i], eyi = ey[i];

        int cnt = 0;
        unsigned minlead = 255u;
        unsigned key = 0xffffffffu;                // (sd<<8)|j, sd < 2^21

        #pragma unroll
        for (int m = 0; m < 8; ++m) {
            int j   = lane + 32 * m;
            int ddx = exi - ex[j], ddy = eyi - ey[j];
            int de  = ddx * ddx + ddy * ddy;
            if (de < 4) {                          // dist < 2.0 <=> sq < 4
                cnt++;
                minlead = min(minlead, (unsigned)j);   // argmax(ov) = first True
                int sdx = sx[j] - exi, sdy = sy[j] - eyi;
                unsigned sd = (unsigned)(sdx * sdx + sdy * sdy);
                key = min(key, (sd << 8) | (unsigned)j);
            }
        }
        cnt     = __reduce_add_sync(0xffffffffu, cnt);
        minlead = __reduce_min_sync(0xffffffffu, minlead);
        key     = __reduce_min_sync(0xffffffffu, key);

        if (lane == 0)
            g_meta[base + i] = (int)(key & 255u) | ((int)minlead << 8) | ((cnt > 1) << 16);
    }
}

// ---------------------------------------------------------------------------
// Kernel 3: finalize coordinates + peak (exact row-major 3x3 fma chain).
// ---------------------------------------------------------------------------
__global__ void __launch_bounds__(128) finalize_kernel(
    const float* __restrict__ depth, const int* __restrict__ points,
    float* __restrict__ out)
{
    const int gid  = blockIdx.x * 128 + threadIdx.x;   // 0..16383
    const int b    = gid >> 8;
    const int base = b * NN;
    const int i    = gid & 255;

    const int meta   = g_meta[gid];
    const int leader = (meta >> 8) & 0xff;
    const bool has   = (meta >> 16) & 1;
    const int wol    = g_meta[base + leader] & 0xff;   // winner[leader]

    int fx, fy;
    if (has) {
        if (i == wol) {
            int2 e = g_end[base + leader];
            fx = e.x; fy = e.y;
        } else {
            int2 s = *(const int2*)(points + gid * 2);
            fx = s.x; fy = s.y;
        }
    } else {
        int2 e = g_end[gid];
        fx = e.x; fy = e.y;
    }

    const float* dep = depth + (size_t)b * HH * WW;
    float acc = 0.0f;
    #pragma unroll
    for (int u = -1; u <= 1; ++u)
        #pragma unroll
        for (int v = -1; v <= 1; ++v) {
            int gy = fy + u, gx = fx + v;
            float val = (gy >= 0 && gy < HH && gx >= 0 && gx < WW)
                            ? __ldg(dep + gy * WW + gx) : 0.0f;
            acc = fmaf(val, W9, acc);
        }

    out[gid * 2 + 0] = (float)fx;
    out[gid * 2 + 1] = (float)fy;
    out[BB * NN * 2 + gid] = acc;
}

// ---------------------------------------------------------------------------
extern "C" void kernel_launch(void* const* d_in, const int* in_sizes, int n_in,
                              void* d_out, int out_size)
{
    const float* depth  = (const float*)d_in[0];   // (64,1,1024,1024) f32
    const int*   points = (const int*)d_in[1];     // (64,256,2) i32
    float* out = (float*)d_out;                    // end (B,N,2) ++ peak (B,N)

    gravity_kernel <<<(BB * NN) / 2, 64>>>(depth, points);
    pairwise_kernel<<<BB * 8,        256>>>(points);
    finalize_kernel<<<(BB * NN) / 128, 128>>>(depth, points, out);
}